// round 1
// baseline (speedup 1.0000x reference)
#include <cuda_runtime.h>
#include <math.h>

// Problem shapes (fixed by the reference)
static constexpr int NB = 4;      // batch
static constexpr int LSEQ = 2048; // sequence length
static constexpr int DIN = 1024;  // input dim (= K of projections)
static constexpr int HDIM = 1024; // q/k head dim
static constexpr int ODIM = 1024; // v/out dim

// Scratch (allocation-free rule: __device__ globals)
__device__ float g_Q[(size_t)NB * LSEQ * HDIM];
__device__ float g_K[(size_t)NB * LSEQ * HDIM];
__device__ float g_V[(size_t)NB * LSEQ * ODIM];
__device__ float g_S[(size_t)NB * LSEQ * LSEQ];

// ---------------------------------------------------------------------------
// 128x128x16 SGEMM, 256 threads, 8x8 microtile per thread.
// A: [M,K] row-major. B: [K,N] row-major (TRANSB=false) or [N,K] row-major
// (TRANSB=true, i.e. C = A * B^T). C: [M,N] row-major.
// All dims assumed multiples of the tile (true for every call here).
// ---------------------------------------------------------------------------
template <bool TRANSB, bool BIAS>
__global__ __launch_bounds__(256, 2)
void sgemm128(const float* __restrict__ A, const float* __restrict__ B,
              const float* __restrict__ bias, float* __restrict__ C,
              int M, int N, int K, float scale,
              size_t sA, size_t sB, size_t sC)
{
    __shared__ float As[16][128];
    __shared__ float Bs[16][128];

    const int z = blockIdx.z;
    A += (size_t)z * sA;
    B += (size_t)z * sB;
    C += (size_t)z * sC;

    const int bm = blockIdx.y * 128;
    const int bn = blockIdx.x * 128;
    const int tid = threadIdx.x;
    const int tx = tid & 15;   // 0..15 -> N direction
    const int ty = tid >> 4;   // 0..15 -> M direction

    float acc[8][8];
#pragma unroll
    for (int i = 0; i < 8; i++)
#pragma unroll
        for (int j = 0; j < 8; j++) acc[i][j] = 0.0f;

    for (int k0 = 0; k0 < K; k0 += 16) {
        // ---- load A tile (128 rows x 16 k), transposed into As[k][m]
#pragma unroll
        for (int s2 = 0; s2 < 2; s2++) {
            int s = tid + s2 * 256;        // 0..511 float4 slots
            int row = s >> 2;              // 0..127
            int kq = (s & 3) * 4;          // 0,4,8,12
            float4 v = *(const float4*)(A + (size_t)(bm + row) * K + k0 + kq);
            As[kq + 0][row] = v.x;
            As[kq + 1][row] = v.y;
            As[kq + 2][row] = v.z;
            As[kq + 3][row] = v.w;
        }
        // ---- load B tile into Bs[k][n]
        if (TRANSB) {
            // B is [N,K] row-major; gather rows of B transposed
#pragma unroll
            for (int s2 = 0; s2 < 2; s2++) {
                int s = tid + s2 * 256;
                int nrow = s >> 2;         // 0..127
                int kq = (s & 3) * 4;
                float4 v = *(const float4*)(B + (size_t)(bn + nrow) * K + k0 + kq);
                Bs[kq + 0][nrow] = v.x;
                Bs[kq + 1][nrow] = v.y;
                Bs[kq + 2][nrow] = v.z;
                Bs[kq + 3][nrow] = v.w;
            }
        } else {
            // B is [K,N] row-major; direct coalesced copy
#pragma unroll
            for (int s2 = 0; s2 < 2; s2++) {
                int s = tid + s2 * 256;
                int krow = s >> 5;         // 0..15 (32 float4 per k-row)
                int c4 = (s & 31) * 4;     // 0..124
                float4 v = *(const float4*)(B + (size_t)(k0 + krow) * N + bn + c4);
                *(float4*)&Bs[krow][c4] = v;
            }
        }
        __syncthreads();

#pragma unroll
        for (int kk = 0; kk < 16; kk++) {
            float4 a0 = *(const float4*)&As[kk][ty * 4];
            float4 a1 = *(const float4*)&As[kk][64 + ty * 4];
            float4 b0 = *(const float4*)&Bs[kk][tx * 4];
            float4 b1 = *(const float4*)&Bs[kk][64 + tx * 4];
            float a[8] = {a0.x, a0.y, a0.z, a0.w, a1.x, a1.y, a1.z, a1.w};
            float b[8] = {b0.x, b0.y, b0.z, b0.w, b1.x, b1.y, b1.z, b1.w};
#pragma unroll
            for (int i = 0; i < 8; i++)
#pragma unroll
                for (int j = 0; j < 8; j++)
                    acc[i][j] = fmaf(a[i], b[j], acc[i][j]);
        }
        __syncthreads();
    }

    // ---- epilogue: C[row][col] = acc*scale (+ bias[col])
#pragma unroll
    for (int i = 0; i < 8; i++) {
        int row = bm + ((i >> 2) * 64) + ty * 4 + (i & 3);
#pragma unroll
        for (int jj = 0; jj < 2; jj++) {
            int col = bn + jj * 64 + tx * 4;
            float4 r;
            r.x = acc[i][jj * 4 + 0] * scale;
            r.y = acc[i][jj * 4 + 1] * scale;
            r.z = acc[i][jj * 4 + 2] * scale;
            r.w = acc[i][jj * 4 + 3] * scale;
            if (BIAS) {
                r.x += bias[col + 0];
                r.y += bias[col + 1];
                r.z += bias[col + 2];
                r.w += bias[col + 3];
            }
            *(float4*)(C + (size_t)row * N + col) = r;
        }
    }
}

// ---------------------------------------------------------------------------
// Row softmax over 2048 columns. One block (256 threads) per row,
// 8 elements per thread held in registers; two block reductions.
// ---------------------------------------------------------------------------
__global__ __launch_bounds__(256)
void softmax_rows2048(float* __restrict__ S)
{
    const size_t row = blockIdx.x;
    float* p = S + row * (size_t)LSEQ;
    const int t = threadIdx.x;

    float v[8];
    float m = -1e30f;
#pragma unroll
    for (int i = 0; i < 8; i++) {
        v[i] = p[t + i * 256];
        m = fmaxf(m, v[i]);
    }

    __shared__ float redm[8];
    __shared__ float reds[8];

    // block max
#pragma unroll
    for (int o = 16; o > 0; o >>= 1)
        m = fmaxf(m, __shfl_xor_sync(0xFFFFFFFFu, m, o));
    if ((t & 31) == 0) redm[t >> 5] = m;
    __syncthreads();
    m = redm[0];
#pragma unroll
    for (int i = 1; i < 8; i++) m = fmaxf(m, redm[i]);

    // exp + block sum
    float s = 0.0f;
#pragma unroll
    for (int i = 0; i < 8; i++) {
        v[i] = __expf(v[i] - m);
        s += v[i];
    }
#pragma unroll
    for (int o = 16; o > 0; o >>= 1)
        s += __shfl_xor_sync(0xFFFFFFFFu, s, o);
    if ((t & 31) == 0) reds[t >> 5] = s;
    __syncthreads();
    s = reds[0];
#pragma unroll
    for (int i = 1; i < 8; i++) s += reds[i];

    const float inv = 1.0f / s;
#pragma unroll
    for (int i = 0; i < 8; i++)
        p[t + i * 256] = v[i] * inv;
}

// ---------------------------------------------------------------------------
extern "C" void kernel_launch(void* const* d_in, const int* in_sizes, int n_in,
                              void* d_out, int out_size)
{
    const float* x  = (const float*)d_in[0];
    const float* Wq = (const float*)d_in[1];
    const float* bq = (const float*)d_in[2];
    const float* Wk = (const float*)d_in[3];
    const float* bk = (const float*)d_in[4];
    const float* Wv = (const float*)d_in[5];
    const float* bv = (const float*)d_in[6];
    float* out = (float*)d_out;

    float *Q, *K, *V, *S;
    cudaGetSymbolAddress((void**)&Q, g_Q);
    cudaGetSymbolAddress((void**)&K, g_K);
    cudaGetSymbolAddress((void**)&V, g_V);
    cudaGetSymbolAddress((void**)&S, g_S);

    const dim3 blk(256);
    const int M = NB * LSEQ;  // 8192

    // Projections: C = x @ W + b     [8192,1024] x [1024,1024]
    sgemm128<false, true><<<dim3(HDIM / 128, M / 128, 1), blk>>>(
        x, Wq, bq, Q, M, HDIM, DIN, 1.0f, 0, 0, 0);
    sgemm128<false, true><<<dim3(HDIM / 128, M / 128, 1), blk>>>(
        x, Wk, bk, K, M, HDIM, DIN, 1.0f, 0, 0, 0);
    sgemm128<false, true><<<dim3(ODIM / 128, M / 128, 1), blk>>>(
        x, Wv, bv, V, M, ODIM, DIN, 1.0f, 0, 0, 0);

    // Scores: S = (Q @ K^T) / sqrt(L)   batched over NB
    const float sc = rsqrtf((float)LSEQ);
    sgemm128<true, false><<<dim3(LSEQ / 128, LSEQ / 128, NB), blk>>>(
        Q, K, nullptr, S, LSEQ, LSEQ, HDIM, sc,
        (size_t)LSEQ * HDIM, (size_t)LSEQ * HDIM, (size_t)LSEQ * LSEQ);

    // Softmax over rows
    softmax_rows2048<<<NB * LSEQ, 256>>>(S);

    // Output: out = S @ V     batched over NB
    sgemm128<false, false><<<dim3(ODIM / 128, LSEQ / 128, NB), blk>>>(
        S, V, nullptr, out, LSEQ, ODIM, LSEQ, 1.0f,
        (size_t)LSEQ * LSEQ, (size_t)LSEQ * ODIM, (size_t)LSEQ * ODIM);
}

// round 3
// speedup vs baseline: 1.8804x; 1.8804x over previous
#include <cuda_runtime.h>
#include <cuda_bf16.h>
#include <cstdint>
#include <math.h>

static constexpr int NB = 4, LSEQ = 2048, DIN = 1024, HDIM = 1024, ODIM = 1024;
static constexpr int MTOT = NB * LSEQ; // 8192

// ---------------- scratch (__device__ globals; no allocation allowed) ------
__device__ __nv_bfloat16 g_xh[(size_t)MTOT * DIN];
__device__ __nv_bfloat16 g_xl[(size_t)MTOT * DIN];
__device__ __nv_bfloat16 g_Wth[(size_t)3 * DIN * HDIM];
__device__ __nv_bfloat16 g_Wtl[(size_t)3 * DIN * HDIM];
__device__ __nv_bfloat16 g_Qh[(size_t)MTOT * HDIM];
__device__ __nv_bfloat16 g_Ql[(size_t)MTOT * HDIM];
__device__ __nv_bfloat16 g_Kh[(size_t)MTOT * HDIM];
__device__ __nv_bfloat16 g_Kl[(size_t)MTOT * HDIM];
__device__ float         g_V [(size_t)MTOT * ODIM];
__device__ __nv_bfloat16 g_Vth[(size_t)NB * ODIM * LSEQ];
__device__ __nv_bfloat16 g_Vtl[(size_t)NB * ODIM * LSEQ];
__device__ float         g_S [(size_t)NB * LSEQ * LSEQ];
__device__ __nv_bfloat16 g_Sh[(size_t)NB * LSEQ * LSEQ];
__device__ __nv_bfloat16 g_Sl[(size_t)NB * LSEQ * LSEQ];

// ---------------- PTX helpers ----------------------------------------------
__device__ __forceinline__ uint32_t smem_u32(const void* p) {
    uint32_t a;
    asm("{ .reg .u64 t; cvta.to.shared.u64 t, %1; cvt.u32.u64 %0, t; }" : "=r"(a) : "l"(p));
    return a;
}
#define CP16(dst, src) \
    asm volatile("cp.async.cg.shared.global [%0], [%1], 16;" :: "r"(dst), "l"(src))
#define CP_COMMIT() asm volatile("cp.async.commit_group;")
#define CP_WAIT1()  asm volatile("cp.async.wait_group 1;")
#define LDSM4(r, addr) \
    asm volatile("ldmatrix.sync.aligned.m8n8.x4.shared.b16 {%0,%1,%2,%3}, [%4];" \
        : "=r"((r)[0]), "=r"((r)[1]), "=r"((r)[2]), "=r"((r)[3]) : "r"(addr))
#define MMA16816(d, a, b0v, b1v) \
    asm volatile("mma.sync.aligned.m16n8k16.row.col.f32.bf16.bf16.f32 " \
        "{%0,%1,%2,%3}, {%4,%5,%6,%7}, {%8,%9}, {%0,%1,%2,%3};" \
        : "+f"((d)[0]), "+f"((d)[1]), "+f"((d)[2]), "+f"((d)[3]) \
        : "r"((a)[0]), "r"((a)[1]), "r"((a)[2]), "r"((a)[3]), "r"(b0v), "r"(b1v))

// ---------------- smem layout for GEMM --------------------------------------
// Per stage: Ah | Al | Bh | Bl, each 128 rows x 32 bf16 padded to 40 (80B/row).
static constexpr uint32_t OP_BYTES = 128 * 80;          // 10240
static constexpr uint32_t STAGE_BYTES = 4 * OP_BYTES;   // 40960
static constexpr int STAGES = 3;
static constexpr uint32_t SMEM_GEMM = STAGES * STAGE_BYTES; // 122880

// ---------------------------------------------------------------------------
// C[M,N] = scale*(Ah+Al)[M,K] @ ((Bh+Bl)[N,K])^T (+bias), 3-pass bf16 split.
// CTA 128x128, BK=32, 8 warps (2x4 -> warp tile 64x32), cp.async 3-stage.
// ---------------------------------------------------------------------------
template <bool BIAS, bool SPLITC>
__global__ __launch_bounds__(256, 1)
void gemm_split(const __nv_bfloat16* __restrict__ Ah, const __nv_bfloat16* __restrict__ Al,
                const __nv_bfloat16* __restrict__ Bh, const __nv_bfloat16* __restrict__ Bl,
                const float* __restrict__ bias,
                float* __restrict__ Cf, __nv_bfloat16* __restrict__ Ch,
                __nv_bfloat16* __restrict__ Cl,
                int K, int lda, int ldb, int ldc, float scale,
                size_t sA, size_t sB, size_t sC)
{
    extern __shared__ char smem[];
    const uint32_t sq = smem_u32(smem);
    const int t = threadIdx.x, lane = t & 31, wid = t >> 5;
    const int bn = blockIdx.x * 128, bm = blockIdx.y * 128, z = blockIdx.z;
    Ah += (size_t)z * sA; Al += (size_t)z * sA;
    Bh += (size_t)z * sB; Bl += (size_t)z * sB;

    // cp.async source bases (bytes). Thread t: row (t>>2) and (t>>2)+64, k-chunk t&3.
    const char* gAh = (const char*)(Ah + (size_t)(bm + (t >> 2)) * lda + (t & 3) * 8);
    const char* gAl = (const char*)(Al + (size_t)(bm + (t >> 2)) * lda + (t & 3) * 8);
    const char* gBh = (const char*)(Bh + (size_t)(bn + (t >> 2)) * ldb + (t & 3) * 8);
    const char* gBl = (const char*)(Bl + (size_t)(bn + (t >> 2)) * ldb + (t & 3) * 8);
    const size_t rA = (size_t)64 * lda * 2, rB = (size_t)64 * ldb * 2;
    const uint32_t dsto = (uint32_t)((t >> 2) * 80 + (t & 3) * 16);

    auto issue = [&](int s) {
        uint32_t sb = sq + (uint32_t)(s % STAGES) * STAGE_BYTES;
        size_t ko = (size_t)s * 64; // 32 elements * 2B along K
        CP16(sb + dsto,                      gAh + ko);
        CP16(sb + dsto + 5120,               gAh + rA + ko);
        CP16(sb + OP_BYTES + dsto,           gAl + ko);
        CP16(sb + OP_BYTES + dsto + 5120,    gAl + rA + ko);
        CP16(sb + 2*OP_BYTES + dsto,         gBh + ko);
        CP16(sb + 2*OP_BYTES + dsto + 5120,  gBh + rB + ko);
        CP16(sb + 3*OP_BYTES + dsto,         gBl + ko);
        CP16(sb + 3*OP_BYTES + dsto + 5120,  gBl + rB + ko);
    };

    float acc[4][4][4];
#pragma unroll
    for (int i = 0; i < 4; i++)
#pragma unroll
        for (int j = 0; j < 4; j++)
#pragma unroll
            for (int r = 0; r < 4; r++) acc[i][j][r] = 0.0f;

    const int NST = K >> 5;
    issue(0); CP_COMMIT();
    issue(1); CP_COMMIT();

    const int m0w = (wid & 1) * 64, n0w = (wid >> 1) * 32;
    const uint32_t aoff = (uint32_t)((m0w + (lane & 15)) * 80 + (lane >> 4) * 16);
    const uint32_t boff = (uint32_t)((n0w + (lane & 15)) * 80 + (lane >> 4) * 16);

    for (int it = 0; it < NST; ++it) {
        CP_WAIT1();
        __syncthreads();
        if (it + 2 < NST) issue(it + 2);
        CP_COMMIT();

        const uint32_t sb = sq + (uint32_t)(it % STAGES) * STAGE_BYTES;
#pragma unroll
        for (int s = 0; s < 2; ++s) {  // two k16 steps per 32-chunk
            uint32_t ah[4][4], al[4][4], bh[2][4], bl[2][4];
#pragma unroll
            for (int tm = 0; tm < 4; ++tm) {
                LDSM4(ah[tm], sb + aoff + tm * 1280u + s * 32u);
                LDSM4(al[tm], sb + OP_BYTES + aoff + tm * 1280u + s * 32u);
            }
#pragma unroll
            for (int tn = 0; tn < 2; ++tn) {
                LDSM4(bh[tn], sb + 2*OP_BYTES + boff + tn * 1280u + s * 32u);
                LDSM4(bl[tn], sb + 3*OP_BYTES + boff + tn * 1280u + s * 32u);
            }
            // pass 1: Ah*Bh
#pragma unroll
            for (int mi = 0; mi < 4; ++mi)
#pragma unroll
                for (int ni = 0; ni < 4; ++ni)
                    MMA16816(acc[mi][ni], ah[mi], bh[ni >> 1][ni & 1], bh[ni >> 1][2 + (ni & 1)]);
            // pass 2: Ah*Bl
#pragma unroll
            for (int mi = 0; mi < 4; ++mi)
#pragma unroll
                for (int ni = 0; ni < 4; ++ni)
                    MMA16816(acc[mi][ni], ah[mi], bl[ni >> 1][ni & 1], bl[ni >> 1][2 + (ni & 1)]);
            // pass 3: Al*Bh
#pragma unroll
            for (int mi = 0; mi < 4; ++mi)
#pragma unroll
                for (int ni = 0; ni < 4; ++ni)
                    MMA16816(acc[mi][ni], al[mi], bh[ni >> 1][ni & 1], bh[ni >> 1][2 + (ni & 1)]);
        }
    }

    // ---- epilogue
    const int lr = lane >> 2, lc = (lane & 3) * 2;
#pragma unroll
    for (int mi = 0; mi < 4; ++mi) {
        const int r0 = bm + m0w + mi * 16 + lr;
#pragma unroll
        for (int ni = 0; ni < 4; ++ni) {
            const int col = bn + n0w + ni * 8 + lc;
            float b0 = 0.f, b1 = 0.f;
            if (BIAS) { b0 = bias[col]; b1 = bias[col + 1]; }
            float v00 = acc[mi][ni][0] * scale + b0, v01 = acc[mi][ni][1] * scale + b1;
            float v10 = acc[mi][ni][2] * scale + b0, v11 = acc[mi][ni][3] * scale + b1;
            const size_t o0 = (size_t)z * sC + (size_t)r0 * ldc + col;
            const size_t o1 = o0 + (size_t)8 * ldc;
            if (SPLITC) {
                __nv_bfloat162 h0 = __floats2bfloat162_rn(v00, v01);
                __nv_bfloat162 h1 = __floats2bfloat162_rn(v10, v11);
                __nv_bfloat162 l0 = __floats2bfloat162_rn(v00 - __bfloat162float(h0.x),
                                                          v01 - __bfloat162float(h0.y));
                __nv_bfloat162 l1 = __floats2bfloat162_rn(v10 - __bfloat162float(h1.x),
                                                          v11 - __bfloat162float(h1.y));
                *(__nv_bfloat162*)(Ch + o0) = h0;
                *(__nv_bfloat162*)(Ch + o1) = h1;
                *(__nv_bfloat162*)(Cl + o0) = l0;
                *(__nv_bfloat162*)(Cl + o1) = l1;
            } else {
                *(float2*)(Cf + o0) = make_float2(v00, v01);
                *(float2*)(Cf + o1) = make_float2(v10, v11);
            }
        }
    }
}

// ---------------------------------------------------------------------------
// Elementwise fp32 -> bf16 hi/lo split (float4 vectorized).
// ---------------------------------------------------------------------------
__global__ __launch_bounds__(256)
void split_hilo(const float4* __restrict__ in, __nv_bfloat162* __restrict__ oh,
                __nv_bfloat162* __restrict__ ol, size_t n4)
{
    size_t i = (size_t)blockIdx.x * blockDim.x + threadIdx.x;
    if (i >= n4) return;
    float4 v = in[i];
    __nv_bfloat162 h0 = __floats2bfloat162_rn(v.x, v.y);
    __nv_bfloat162 h1 = __floats2bfloat162_rn(v.z, v.w);
    __nv_bfloat162 l0 = __floats2bfloat162_rn(v.x - __bfloat162float(h0.x),
                                              v.y - __bfloat162float(h0.y));
    __nv_bfloat162 l1 = __floats2bfloat162_rn(v.z - __bfloat162float(h1.x),
                                              v.w - __bfloat162float(h1.y));
    oh[i * 2] = h0; oh[i * 2 + 1] = h1;
    ol[i * 2] = l0; ol[i * 2 + 1] = l1;
}

// ---------------------------------------------------------------------------
// Transpose + split: in [R,C] fp32 (batch stride R*C) -> oh/ol [C,R] bf16.
// ---------------------------------------------------------------------------
__global__ __launch_bounds__(256)
void transpose_split(const float* __restrict__ in, __nv_bfloat16* __restrict__ oh,
                     __nv_bfloat16* __restrict__ ol, int R, int Ccols)
{
    __shared__ float tb[32][33];
    const size_t base = (size_t)blockIdx.z * R * Ccols;
    const int bx = blockIdx.x * 32, by = blockIdx.y * 32;
    const int tx = threadIdx.x & 31, ty = threadIdx.x >> 5;
#pragma unroll
    for (int j = 0; j < 4; j++) {
        int r = ty + j * 8;
        tb[r][tx] = in[base + (size_t)(by + r) * Ccols + bx + tx];
    }
    __syncthreads();
#pragma unroll
    for (int j = 0; j < 4; j++) {
        int r = ty + j * 8;
        float v = tb[tx][r];
        size_t o = base + (size_t)(bx + r) * R + by + tx;
        __nv_bfloat16 h = __float2bfloat16(v);
        oh[o] = h;
        ol[o] = __float2bfloat16(v - __bfloat162float(h));
    }
}

// ---------------------------------------------------------------------------
// Row softmax over 2048 cols; writes bf16 hi/lo split.
// ---------------------------------------------------------------------------
__global__ __launch_bounds__(256)
void softmax_split2048(const float* __restrict__ S, __nv_bfloat16* __restrict__ Sh,
                       __nv_bfloat16* __restrict__ Sl)
{
    const size_t row = blockIdx.x;
    const float* p = S + row * (size_t)LSEQ;
    __nv_bfloat16* ph = Sh + row * (size_t)LSEQ;
    __nv_bfloat16* pl = Sl + row * (size_t)LSEQ;
    const int t = threadIdx.x;
    float v[8];
    float m = -1e30f;
#pragma unroll
    for (int i = 0; i < 8; i++) { v[i] = p[t + i * 256]; m = fmaxf(m, v[i]); }
    __shared__ float redm[8], reds[8];
#pragma unroll
    for (int o = 16; o > 0; o >>= 1) m = fmaxf(m, __shfl_xor_sync(0xFFFFFFFFu, m, o));
    if ((t & 31) == 0) redm[t >> 5] = m;
    __syncthreads();
    m = redm[0];
#pragma unroll
    for (int i = 1; i < 8; i++) m = fmaxf(m, redm[i]);
    float s = 0.0f;
#pragma unroll
    for (int i = 0; i < 8; i++) { v[i] = __expf(v[i] - m); s += v[i]; }
#pragma unroll
    for (int o = 16; o > 0; o >>= 1) s += __shfl_xor_sync(0xFFFFFFFFu, s, o);
    if ((t & 31) == 0) reds[t >> 5] = s;
    __syncthreads();
    s = reds[0];
#pragma unroll
    for (int i = 1; i < 8; i++) s += reds[i];
    const float inv = 1.0f / s;
#pragma unroll
    for (int i = 0; i < 8; i++) {
        float val = v[i] * inv;
        __nv_bfloat16 h = __float2bfloat16(val);
        ph[t + i * 256] = h;
        pl[t + i * 256] = __float2bfloat16(val - __bfloat162float(h));
    }
}

// ---------------------------------------------------------------------------
extern "C" void kernel_launch(void* const* d_in, const int* in_sizes, int n_in,
                              void* d_out, int out_size)
{
    const float* x  = (const float*)d_in[0];
    const float* Wq = (const float*)d_in[1];
    const float* bq = (const float*)d_in[2];
    const float* Wk = (const float*)d_in[3];
    const float* bk = (const float*)d_in[4];
    const float* Wv = (const float*)d_in[5];
    const float* bv = (const float*)d_in[6];
    float* out = (float*)d_out;

    __nv_bfloat16 *xh, *xl, *Wth, *Wtl, *Qh, *Ql, *Kh, *Kl, *Vth, *Vtl, *Sh, *Sl;
    float *V, *S;
    cudaGetSymbolAddress((void**)&xh, g_xh);   cudaGetSymbolAddress((void**)&xl, g_xl);
    cudaGetSymbolAddress((void**)&Wth, g_Wth); cudaGetSymbolAddress((void**)&Wtl, g_Wtl);
    cudaGetSymbolAddress((void**)&Qh, g_Qh);   cudaGetSymbolAddress((void**)&Ql, g_Ql);
    cudaGetSymbolAddress((void**)&Kh, g_Kh);   cudaGetSymbolAddress((void**)&Kl, g_Kl);
    cudaGetSymbolAddress((void**)&V, g_V);
    cudaGetSymbolAddress((void**)&Vth, g_Vth); cudaGetSymbolAddress((void**)&Vtl, g_Vtl);
    cudaGetSymbolAddress((void**)&S, g_S);
    cudaGetSymbolAddress((void**)&Sh, g_Sh);   cudaGetSymbolAddress((void**)&Sl, g_Sl);

    cudaFuncSetAttribute(gemm_split<true, true>,   cudaFuncAttributeMaxDynamicSharedMemorySize, SMEM_GEMM);
    cudaFuncSetAttribute(gemm_split<true, false>,  cudaFuncAttributeMaxDynamicSharedMemorySize, SMEM_GEMM);
    cudaFuncSetAttribute(gemm_split<false, false>, cudaFuncAttributeMaxDynamicSharedMemorySize, SMEM_GEMM);

    const size_t WSZ = (size_t)DIN * HDIM;

    // 1) split x; transpose+split weights
    {
        size_t n4 = (size_t)MTOT * DIN / 4;
        split_hilo<<<(unsigned)((n4 + 255) / 256), 256>>>(
            (const float4*)x, (__nv_bfloat162*)xh, (__nv_bfloat162*)xl, n4);
    }
    transpose_split<<<dim3(HDIM/32, DIN/32, 1), 256>>>(Wq, Wth + 0*WSZ, Wtl + 0*WSZ, DIN, HDIM);
    transpose_split<<<dim3(HDIM/32, DIN/32, 1), 256>>>(Wk, Wth + 1*WSZ, Wtl + 1*WSZ, DIN, HDIM);
    transpose_split<<<dim3(HDIM/32, DIN/32, 1), 256>>>(Wv, Wth + 2*WSZ, Wtl + 2*WSZ, DIN, HDIM);

    // 2) projections (M=8192, N=1024, K=1024). Q,K write split; V writes fp32.
    const dim3 gproj(HDIM / 128, MTOT / 128, 1);
    gemm_split<true, true><<<gproj, 256, SMEM_GEMM>>>(
        xh, xl, Wth + 0*WSZ, Wtl + 0*WSZ, bq, nullptr, Qh, Ql,
        DIN, DIN, DIN, HDIM, 1.0f, 0, 0, 0);
    gemm_split<true, true><<<gproj, 256, SMEM_GEMM>>>(
        xh, xl, Wth + 1*WSZ, Wtl + 1*WSZ, bk, nullptr, Kh, Kl,
        DIN, DIN, DIN, HDIM, 1.0f, 0, 0, 0);
    gemm_split<true, false><<<gproj, 256, SMEM_GEMM>>>(
        xh, xl, Wth + 2*WSZ, Wtl + 2*WSZ, bv, V, nullptr, nullptr,
        DIN, DIN, DIN, ODIM, 1.0f, 0, 0, 0);

    // 3) V transpose+split per batch: [L,O] -> [O,L]
    transpose_split<<<dim3(ODIM/32, LSEQ/32, NB), 256>>>(V, Vth, Vtl, LSEQ, ODIM);

    // 4) S = (Q @ K^T)/sqrt(L), batched, fp32 out
    gemm_split<false, false><<<dim3(LSEQ/128, LSEQ/128, NB), 256, SMEM_GEMM>>>(
        Qh, Ql, Kh, Kl, nullptr, S, nullptr, nullptr,
        HDIM, HDIM, HDIM, LSEQ, rsqrtf((float)LSEQ),
        (size_t)LSEQ * HDIM, (size_t)LSEQ * HDIM, (size_t)LSEQ * LSEQ);

    // 5) softmax -> Sh/Sl
    softmax_split2048<<<NB * LSEQ, 256>>>(S, Sh, Sl);

    // 6) out = S @ V (A=[L,L], B=Vt [O,L]), fp32 out
    gemm_split<false, false><<<dim3(ODIM/128, LSEQ/128, NB), 256, SMEM_GEMM>>>(
        Sh, Sl, Vth, Vtl, nullptr, out, nullptr, nullptr,
        LSEQ, LSEQ, LSEQ, ODIM, 1.0f,
        (size_t)LSEQ * LSEQ, (size_t)ODIM * LSEQ, (size_t)LSEQ * ODIM);
}

// round 4
// speedup vs baseline: 2.0962x; 1.1148x over previous
#include <cuda_runtime.h>
#include <cuda_bf16.h>
#include <cstdint>
#include <math.h>

static constexpr int NB = 4, LSEQ = 2048, DIN = 1024, HDIM = 1024, ODIM = 1024;
static constexpr int MTOT = NB * LSEQ; // 8192

// ---------------- scratch (__device__ globals; no allocation allowed) ------
__device__ __nv_bfloat16 g_xh[(size_t)MTOT * DIN];
__device__ __nv_bfloat16 g_xl[(size_t)MTOT * DIN];
__device__ __nv_bfloat16 g_Wth[(size_t)3 * DIN * HDIM];   // [3*H, D] rows
__device__ __nv_bfloat16 g_Wtl[(size_t)3 * DIN * HDIM];
__device__ float         g_bcat[3 * HDIM];
__device__ __nv_bfloat16 g_Qh[(size_t)MTOT * HDIM];
__device__ __nv_bfloat16 g_Ql[(size_t)MTOT * HDIM];
__device__ __nv_bfloat16 g_Kh[(size_t)MTOT * HDIM];
__device__ __nv_bfloat16 g_Kl[(size_t)MTOT * HDIM];
__device__ __nv_bfloat16 g_Vh[(size_t)MTOT * ODIM];
__device__ __nv_bfloat16 g_Vl[(size_t)MTOT * ODIM];
__device__ __nv_bfloat16 g_Vth[(size_t)NB * ODIM * LSEQ];
__device__ __nv_bfloat16 g_Vtl[(size_t)NB * ODIM * LSEQ];
__device__ float         g_S [(size_t)NB * LSEQ * LSEQ];
__device__ __nv_bfloat16 g_Sh[(size_t)NB * LSEQ * LSEQ];
__device__ __nv_bfloat16 g_Sl[(size_t)NB * LSEQ * LSEQ];

struct SplitOut {
    __nv_bfloat16 *h0, *l0, *h1, *l1, *h2, *l2;
};

// ---------------- PTX helpers ----------------------------------------------
__device__ __forceinline__ uint32_t smem_u32(const void* p) {
    uint32_t a;
    asm("{ .reg .u64 t; cvta.to.shared.u64 t, %1; cvt.u32.u64 %0, t; }" : "=r"(a) : "l"(p));
    return a;
}
#define CP16(dst, src) \
    asm volatile("cp.async.cg.shared.global [%0], [%1], 16;" :: "r"(dst), "l"(src))
#define CP_COMMIT() asm volatile("cp.async.commit_group;")
#define CP_WAIT0()  asm volatile("cp.async.wait_group 0;")
#define LDSM4(r, addr) \
    asm volatile("ldmatrix.sync.aligned.m8n8.x4.shared.b16 {%0,%1,%2,%3}, [%4];" \
        : "=r"((r)[0]), "=r"((r)[1]), "=r"((r)[2]), "=r"((r)[3]) : "r"(addr))
#define MMA16816(d, a, b0v, b1v) \
    asm volatile("mma.sync.aligned.m16n8k16.row.col.f32.bf16.bf16.f32 " \
        "{%0,%1,%2,%3}, {%4,%5,%6,%7}, {%8,%9}, {%0,%1,%2,%3};" \
        : "+f"((d)[0]), "+f"((d)[1]), "+f"((d)[2]), "+f"((d)[3]) \
        : "r"((a)[0]), "r"((a)[1]), "r"((a)[2]), "r"((a)[3]), "r"(b0v), "r"(b1v))

// ---------------- smem layout for GEMM --------------------------------------
// Per stage: Ah | Al | Bh | Bl, each 128 rows x 32 bf16 padded to 40 (80B/row).
static constexpr uint32_t OP_BYTES = 128 * 80;          // 10240
static constexpr uint32_t STAGE_BYTES = 4 * OP_BYTES;   // 40960
static constexpr uint32_t SMEM_GEMM = 2 * STAGE_BYTES;  // 81920 (2-stage)

// ---------------------------------------------------------------------------
// Persistent split-bf16 GEMM: C = scale*(Ah+Al)[M,K] @ ((Bh+Bl)[N,K])^T (+bias)
// 3 MMA passes (AhBh + AhBl + AlBh). CTA tile 128x128, BK=32, 8 warps,
// 2-stage cp.async, 2 CTAs/SM, grid-stride over (gx,gy,gz) tiles.
// SPLITC: write bf16 hi/lo to per-1024-column-segment outputs (proj QKV).
// ---------------------------------------------------------------------------
template <bool BIAS, bool SPLITC>
__global__ __launch_bounds__(256, 2)
void gemm_split(const __nv_bfloat16* __restrict__ Ah, const __nv_bfloat16* __restrict__ Al,
                const __nv_bfloat16* __restrict__ Bh, const __nv_bfloat16* __restrict__ Bl,
                const float* __restrict__ bias, float* __restrict__ Cf, SplitOut so,
                int K, int lda, int ldb, int ldc, float scale,
                size_t sA, size_t sB, size_t sC,
                int gx, int gy, int gz)
{
    extern __shared__ char smem[];
    const uint32_t sq = smem_u32(smem);
    const int t = threadIdx.x, lane = t & 31, wid = t >> 5;
    const int NST = K >> 5;
    const int m0w = (wid & 1) * 64, n0w = (wid >> 1) * 32;
    const uint32_t aoff = (uint32_t)((m0w + (lane & 15)) * 80 + (lane >> 4) * 16);
    const uint32_t boff = (uint32_t)((n0w + (lane & 15)) * 80 + (lane >> 4) * 16);
    const uint32_t dsto = (uint32_t)((t >> 2) * 80 + (t & 3) * 16);
    const int ntiles = gx * gy * gz;

    for (int tile = blockIdx.x; tile < ntiles; tile += gridDim.x) {
        const int bn = (tile % gx) * 128;
        const int tyz = tile / gx;
        const int bm = (tyz % gy) * 128;
        const int z = tyz / gy;

        const char* gAh = (const char*)(Ah + (size_t)z * sA + (size_t)(bm + (t >> 2)) * lda + (t & 3) * 8);
        const char* gAl = (const char*)(Al + (size_t)z * sA + (size_t)(bm + (t >> 2)) * lda + (t & 3) * 8);
        const char* gBh = (const char*)(Bh + (size_t)z * sB + (size_t)(bn + (t >> 2)) * ldb + (t & 3) * 8);
        const char* gBl = (const char*)(Bl + (size_t)z * sB + (size_t)(bn + (t >> 2)) * ldb + (t & 3) * 8);
        const size_t rA = (size_t)64 * lda * 2, rB = (size_t)64 * ldb * 2;

        auto issue = [&](int s) {
            uint32_t sb = sq + (uint32_t)(s & 1) * STAGE_BYTES;
            size_t ko = (size_t)s * 64;
            CP16(sb + dsto,                       gAh + ko);
            CP16(sb + dsto + 5120,                gAh + rA + ko);
            CP16(sb + OP_BYTES + dsto,            gAl + ko);
            CP16(sb + OP_BYTES + dsto + 5120,     gAl + rA + ko);
            CP16(sb + 2*OP_BYTES + dsto,          gBh + ko);
            CP16(sb + 2*OP_BYTES + dsto + 5120,   gBh + rB + ko);
            CP16(sb + 3*OP_BYTES + dsto,          gBl + ko);
            CP16(sb + 3*OP_BYTES + dsto + 5120,   gBl + rB + ko);
        };

        float acc[4][4][4];
#pragma unroll
        for (int i = 0; i < 4; i++)
#pragma unroll
            for (int j = 0; j < 4; j++)
#pragma unroll
                for (int r = 0; r < 4; r++) acc[i][j][r] = 0.0f;

        issue(0); CP_COMMIT();

        for (int it = 0; it < NST; ++it) {
            CP_WAIT0();          // stage 'it' resident (only group outstanding)
            __syncthreads();     // all warps done with buffer (it+1)&1 from it-1
            if (it + 1 < NST) { issue(it + 1); CP_COMMIT(); }

            const uint32_t sb = sq + (uint32_t)(it & 1) * STAGE_BYTES;
#pragma unroll
            for (int s = 0; s < 2; ++s) {  // two k16 steps per 32-chunk
                uint32_t ah[4][4], bh[2][4], bl[2][4];
#pragma unroll
                for (int tm = 0; tm < 4; ++tm)
                    LDSM4(ah[tm], sb + aoff + tm * 1280u + s * 32u);
#pragma unroll
                for (int tn = 0; tn < 2; ++tn) {
                    LDSM4(bh[tn], sb + 2*OP_BYTES + boff + tn * 1280u + s * 32u);
                    LDSM4(bl[tn], sb + 3*OP_BYTES + boff + tn * 1280u + s * 32u);
                }
                // pass 1: Ah*Bh
#pragma unroll
                for (int mi = 0; mi < 4; ++mi)
#pragma unroll
                    for (int ni = 0; ni < 4; ++ni)
                        MMA16816(acc[mi][ni], ah[mi], bh[ni >> 1][ni & 1], bh[ni >> 1][2 + (ni & 1)]);
                // pass 2: Ah*Bl
#pragma unroll
                for (int mi = 0; mi < 4; ++mi)
#pragma unroll
                    for (int ni = 0; ni < 4; ++ni)
                        MMA16816(acc[mi][ni], ah[mi], bl[ni >> 1][ni & 1], bl[ni >> 1][2 + (ni & 1)]);
                // pass 3: Al*Bh (load al late to cap register pressure)
                uint32_t al[4][4];
#pragma unroll
                for (int tm = 0; tm < 4; ++tm)
                    LDSM4(al[tm], sb + OP_BYTES + aoff + tm * 1280u + s * 32u);
#pragma unroll
                for (int mi = 0; mi < 4; ++mi)
#pragma unroll
                    for (int ni = 0; ni < 4; ++ni)
                        MMA16816(acc[mi][ni], al[mi], bh[ni >> 1][ni & 1], bh[ni >> 1][2 + (ni & 1)]);
            }
        }

        // ---- epilogue
        const int lr = lane >> 2, lc = (lane & 3) * 2;
#pragma unroll
        for (int mi = 0; mi < 4; ++mi) {
            const int r0 = bm + m0w + mi * 16 + lr;
#pragma unroll
            for (int ni = 0; ni < 4; ++ni) {
                const int col = bn + n0w + ni * 8 + lc;
                float b0 = 0.f, b1 = 0.f;
                if (BIAS) { b0 = bias[col]; b1 = bias[col + 1]; }
                float v00 = acc[mi][ni][0] * scale + b0, v01 = acc[mi][ni][1] * scale + b1;
                float v10 = acc[mi][ni][2] * scale + b0, v11 = acc[mi][ni][3] * scale + b1;
                if (SPLITC) {
                    const int seg = col >> 10, lcol = col & 1023;
                    __nv_bfloat16* Ch = seg == 0 ? so.h0 : (seg == 1 ? so.h1 : so.h2);
                    __nv_bfloat16* Cl = seg == 0 ? so.l0 : (seg == 1 ? so.l1 : so.l2);
                    const size_t o0 = (size_t)r0 * 1024 + lcol;
                    const size_t o1 = o0 + (size_t)8 * 1024;
                    __nv_bfloat162 h0 = __floats2bfloat162_rn(v00, v01);
                    __nv_bfloat162 h1 = __floats2bfloat162_rn(v10, v11);
                    __nv_bfloat162 l0 = __floats2bfloat162_rn(v00 - __bfloat162float(h0.x),
                                                              v01 - __bfloat162float(h0.y));
                    __nv_bfloat162 l1 = __floats2bfloat162_rn(v10 - __bfloat162float(h1.x),
                                                              v11 - __bfloat162float(h1.y));
                    *(__nv_bfloat162*)(Ch + o0) = h0;
                    *(__nv_bfloat162*)(Ch + o1) = h1;
                    *(__nv_bfloat162*)(Cl + o0) = l0;
                    *(__nv_bfloat162*)(Cl + o1) = l1;
                } else {
                    const size_t o0 = (size_t)z * sC + (size_t)r0 * ldc + col;
                    const size_t o1 = o0 + (size_t)8 * ldc;
                    *(float2*)(Cf + o0) = make_float2(v00, v01);
                    *(float2*)(Cf + o1) = make_float2(v10, v11);
                }
            }
        }
        // next tile's issue(0) targets buf0 whose last readers synced at it=NST-1;
        // first in-loop sync of next tile gates buf1 reuse.
    }
}

// ---------------------------------------------------------------------------
__global__ __launch_bounds__(256)
void split_hilo(const float4* __restrict__ in, __nv_bfloat162* __restrict__ oh,
                __nv_bfloat162* __restrict__ ol, size_t n4)
{
    size_t i = (size_t)blockIdx.x * blockDim.x + threadIdx.x;
    if (i >= n4) return;
    float4 v = in[i];
    __nv_bfloat162 h0 = __floats2bfloat162_rn(v.x, v.y);
    __nv_bfloat162 h1 = __floats2bfloat162_rn(v.z, v.w);
    __nv_bfloat162 l0 = __floats2bfloat162_rn(v.x - __bfloat162float(h0.x),
                                              v.y - __bfloat162float(h0.y));
    __nv_bfloat162 l1 = __floats2bfloat162_rn(v.z - __bfloat162float(h1.x),
                                              v.w - __bfloat162float(h1.y));
    oh[i * 2] = h0; oh[i * 2 + 1] = h1;
    ol[i * 2] = l0; ol[i * 2 + 1] = l1;
}

// Transpose + split: in [R,C] fp32 -> oh/ol [C,R] bf16 (batch stride R*C).
__global__ __launch_bounds__(256)
void transpose_split(const float* __restrict__ in, __nv_bfloat16* __restrict__ oh,
                     __nv_bfloat16* __restrict__ ol, int R, int Ccols)
{
    __shared__ float tb[32][33];
    const size_t base = (size_t)blockIdx.z * R * Ccols;
    const int bx = blockIdx.x * 32, by = blockIdx.y * 32;
    const int tx = threadIdx.x & 31, ty = threadIdx.x >> 5;
#pragma unroll
    for (int j = 0; j < 4; j++) {
        int r = ty + j * 8;
        tb[r][tx] = in[base + (size_t)(by + r) * Ccols + bx + tx];
    }
    __syncthreads();
#pragma unroll
    for (int j = 0; j < 4; j++) {
        int r = ty + j * 8;
        float v = tb[tx][r];
        size_t o = base + (size_t)(bx + r) * R + by + tx;
        __nv_bfloat16 h = __float2bfloat16(v);
        oh[o] = h;
        ol[o] = __float2bfloat16(v - __bfloat162float(h));
    }
}

// Transpose + re-split from bf16 hi/lo input: in (ih+il) [R,C] -> oh/ol [C,R].
__global__ __launch_bounds__(256)
void transpose_resplit(const __nv_bfloat16* __restrict__ ih, const __nv_bfloat16* __restrict__ il,
                       __nv_bfloat16* __restrict__ oh, __nv_bfloat16* __restrict__ ol,
                       int R, int Ccols)
{
    __shared__ float tb[32][33];
    const size_t base = (size_t)blockIdx.z * R * Ccols;
    const int bx = blockIdx.x * 32, by = blockIdx.y * 32;
    const int tx = threadIdx.x & 31, ty = threadIdx.x >> 5;
#pragma unroll
    for (int j = 0; j < 4; j++) {
        int r = ty + j * 8;
        size_t idx = base + (size_t)(by + r) * Ccols + bx + tx;
        tb[r][tx] = __bfloat162float(ih[idx]) + __bfloat162float(il[idx]);
    }
    __syncthreads();
#pragma unroll
    for (int j = 0; j < 4; j++) {
        int r = ty + j * 8;
        float v = tb[tx][r];
        size_t o = base + (size_t)(bx + r) * R + by + tx;
        __nv_bfloat16 h = __float2bfloat16(v);
        oh[o] = h;
        ol[o] = __float2bfloat16(v - __bfloat162float(h));
    }
}

__global__ void concat_bias(const float* __restrict__ a, const float* __restrict__ b,
                            const float* __restrict__ c, float* __restrict__ o)
{
    int i = blockIdx.x * 256 + threadIdx.x;
    if (i < 1024) o[i] = a[i];
    else if (i < 2048) o[i] = b[i - 1024];
    else if (i < 3072) o[i] = c[i - 2048];
}

// Row softmax over 2048 cols; writes bf16 hi/lo split.
__global__ __launch_bounds__(256)
void softmax_split2048(const float* __restrict__ S, __nv_bfloat16* __restrict__ Sh,
                       __nv_bfloat16* __restrict__ Sl)
{
    const size_t row = blockIdx.x;
    const float* p = S + row * (size_t)LSEQ;
    __nv_bfloat16* ph = Sh + row * (size_t)LSEQ;
    __nv_bfloat16* pl = Sl + row * (size_t)LSEQ;
    const int t = threadIdx.x;
    float v[8];
    float m = -1e30f;
#pragma unroll
    for (int i = 0; i < 8; i++) { v[i] = p[t + i * 256]; m = fmaxf(m, v[i]); }
    __shared__ float redm[8], reds[8];
#pragma unroll
    for (int o = 16; o > 0; o >>= 1) m = fmaxf(m, __shfl_xor_sync(0xFFFFFFFFu, m, o));
    if ((t & 31) == 0) redm[t >> 5] = m;
    __syncthreads();
    m = redm[0];
#pragma unroll
    for (int i = 1; i < 8; i++) m = fmaxf(m, redm[i]);
    float s = 0.0f;
#pragma unroll
    for (int i = 0; i < 8; i++) { v[i] = __expf(v[i] - m); s += v[i]; }
#pragma unroll
    for (int o = 16; o > 0; o >>= 1) s += __shfl_xor_sync(0xFFFFFFFFu, s, o);
    if ((t & 31) == 0) reds[t >> 5] = s;
    __syncthreads();
    s = reds[0];
#pragma unroll
    for (int i = 1; i < 8; i++) s += reds[i];
    const float inv = 1.0f / s;
#pragma unroll
    for (int i = 0; i < 8; i++) {
        float val = v[i] * inv;
        __nv_bfloat16 h = __float2bfloat16(val);
        ph[t + i * 256] = h;
        pl[t + i * 256] = __float2bfloat16(val - __bfloat162float(h));
    }
}

// ---------------------------------------------------------------------------
extern "C" void kernel_launch(void* const* d_in, const int* in_sizes, int n_in,
                              void* d_out, int out_size)
{
    const float* x  = (const float*)d_in[0];
    const float* Wq = (const float*)d_in[1];
    const float* bq = (const float*)d_in[2];
    const float* Wk = (const float*)d_in[3];
    const float* bk = (const float*)d_in[4];
    const float* Wv = (const float*)d_in[5];
    const float* bv = (const float*)d_in[6];
    float* out = (float*)d_out;

    __nv_bfloat16 *xh, *xl, *Wth, *Wtl, *Qh, *Ql, *Kh, *Kl, *Vh, *Vl, *Vth, *Vtl, *Sh, *Sl;
    float *S, *bcat;
    cudaGetSymbolAddress((void**)&xh, g_xh);   cudaGetSymbolAddress((void**)&xl, g_xl);
    cudaGetSymbolAddress((void**)&Wth, g_Wth); cudaGetSymbolAddress((void**)&Wtl, g_Wtl);
    cudaGetSymbolAddress((void**)&bcat, g_bcat);
    cudaGetSymbolAddress((void**)&Qh, g_Qh);   cudaGetSymbolAddress((void**)&Ql, g_Ql);
    cudaGetSymbolAddress((void**)&Kh, g_Kh);   cudaGetSymbolAddress((void**)&Kl, g_Kl);
    cudaGetSymbolAddress((void**)&Vh, g_Vh);   cudaGetSymbolAddress((void**)&Vl, g_Vl);
    cudaGetSymbolAddress((void**)&Vth, g_Vth); cudaGetSymbolAddress((void**)&Vtl, g_Vtl);
    cudaGetSymbolAddress((void**)&S, g_S);
    cudaGetSymbolAddress((void**)&Sh, g_Sh);   cudaGetSymbolAddress((void**)&Sl, g_Sl);

    cudaFuncSetAttribute(gemm_split<true, true>,   cudaFuncAttributeMaxDynamicSharedMemorySize, SMEM_GEMM);
    cudaFuncSetAttribute(gemm_split<false, false>, cudaFuncAttributeMaxDynamicSharedMemorySize, SMEM_GEMM);

    const size_t WSZ = (size_t)DIN * HDIM;
    const int PGRID = 296; // 2 CTAs/SM * 148 SMs
    SplitOut soProj{Qh, Ql, Kh, Kl, Vh, Vl};
    SplitOut soNone{nullptr, nullptr, nullptr, nullptr, nullptr, nullptr};

    // 1) preps: split x, transpose+split W's, concat bias
    {
        size_t n4 = (size_t)MTOT * DIN / 4;
        split_hilo<<<(unsigned)((n4 + 255) / 256), 256>>>(
            (const float4*)x, (__nv_bfloat162*)xh, (__nv_bfloat162*)xl, n4);
    }
    transpose_split<<<dim3(HDIM/32, DIN/32, 1), 256>>>(Wq, Wth + 0*WSZ, Wtl + 0*WSZ, DIN, HDIM);
    transpose_split<<<dim3(HDIM/32, DIN/32, 1), 256>>>(Wk, Wth + 1*WSZ, Wtl + 1*WSZ, DIN, HDIM);
    transpose_split<<<dim3(HDIM/32, DIN/32, 1), 256>>>(Wv, Wth + 2*WSZ, Wtl + 2*WSZ, DIN, HDIM);
    concat_bias<<<12, 256>>>(bq, bk, bv, bcat);

    // 2) merged QKV projection: M=8192, N=3072, K=1024 -> split outputs
    gemm_split<true, true><<<PGRID, 256, SMEM_GEMM>>>(
        xh, xl, Wth, Wtl, bcat, nullptr, soProj,
        DIN, DIN, DIN, 1024, 1.0f, 0, 0, 0,
        3072 / 128, MTOT / 128, 1);

    // 3) V transpose+re-split per batch: [L,O] -> [O,L]
    transpose_resplit<<<dim3(ODIM/32, LSEQ/32, NB), 256>>>(Vh, Vl, Vth, Vtl, LSEQ, ODIM);

    // 4) S = (Q @ K^T)/sqrt(L), batched, fp32 out
    gemm_split<false, false><<<PGRID, 256, SMEM_GEMM>>>(
        Qh, Ql, Kh, Kl, nullptr, S, soNone,
        HDIM, HDIM, HDIM, LSEQ, rsqrtf((float)LSEQ),
        (size_t)LSEQ * HDIM, (size_t)LSEQ * HDIM, (size_t)LSEQ * LSEQ,
        LSEQ / 128, LSEQ / 128, NB);

    // 5) softmax -> Sh/Sl
    softmax_split2048<<<NB * LSEQ, 256>>>(S, Sh, Sl);

    // 6) out = S @ V^T (A=Sh/Sl [L,L], B=Vt [O,L]), fp32 out
    gemm_split<false, false><<<PGRID, 256, SMEM_GEMM>>>(
        Sh, Sl, Vth, Vtl, nullptr, out, soNone,
        LSEQ, LSEQ, LSEQ, ODIM, 1.0f,
        (size_t)LSEQ * LSEQ, (size_t)ODIM * LSEQ, (size_t)LSEQ * ODIM,
        ODIM / 128, LSEQ / 128, NB);
}